// round 17
// baseline (speedup 1.0000x reference)
#include <cuda_runtime.h>
#include <cuda_bf16.h>
#include <math.h>
#include <stdint.h>

#define T_  1024
#define B_  128
#define D_  512
#define H_  256
#define TB_ (T_ * B_)      // 131072
#define G4_ (4 * H_)       // 1024

// ---------------- scratch (device globals; no cudaMalloc allowed) ----------
__device__ uint32_t g_xp [(size_t)TB_ * D_];   // x split-packed (hi<<16|lo)
__device__ uint32_t g_hb [(size_t)TB_ * H_];   // tanh(fc) packed
__device__ float    g_gx [(size_t)TB_ * G4_];  // gate inputs (f32, recur reads)
__device__ uint32_t g_hsb[(size_t)TB_ * H_];   // recurrence out packed
__device__ uint32_t g_z0b[(size_t)TB_ * H_];   // classifier tmp packed
__device__ float    g_z1 [(size_t)TB_ * H_];   // classifier tmp f32
__device__ uint32_t g_Wxp[G4_ * H_];           // packed input weights (f,i,u,o)
__device__ float    g_Wh [G4_ * H_];           // recurrent weights f32
__device__ float    g_bias[G4_];               // packed biases
__device__ uint32_t g_fcwp[H_ * D_];
__device__ uint32_t g_w0p[H_ * H_];
__device__ uint32_t g_w1p[H_ * H_];
__device__ uint32_t g_hxp[2 * B_ * H_];        // double-buffered hx (packed u32)
__device__ unsigned g_bar_in [16 * 32];        // per-group barrier (128B padded)
__device__ unsigned g_bar_gen[16 * 32];

// ================= helpers ==================================================
__device__ __forceinline__ uint32_t smem_u32(const void* p) {
    uint32_t a;
    asm("{ .reg .u64 t; cvta.to.shared.u64 t, %1; cvt.u32.u64 %0, t; }"
        : "=r"(a) : "l"(p));
    return a;
}

__device__ __forceinline__ void mma_bf16(float* c, const uint32_t* a,
                                         const uint32_t* b) {
    asm volatile(
        "mma.sync.aligned.m16n8k16.row.col.f32.bf16.bf16.f32 "
        "{%0,%1,%2,%3}, {%4,%5,%6,%7}, {%8,%9}, {%0,%1,%2,%3};"
        : "+f"(c[0]), "+f"(c[1]), "+f"(c[2]), "+f"(c[3])
        : "r"(a[0]), "r"(a[1]), "r"(a[2]), "r"(a[3]), "r"(b[0]), "r"(b[1]));
}

__device__ __forceinline__ void ldsm4(uint32_t* d, uint32_t addr) {
    asm volatile("ldmatrix.sync.aligned.m8n8.x4.shared.b16 {%0,%1,%2,%3}, [%4];"
        : "=r"(d[0]), "=r"(d[1]), "=r"(d[2]), "=r"(d[3]) : "r"(addr));
}

// split-pack one float: (bf16_hi << 16) | bf16_lo
__device__ __forceinline__ uint32_t pk(float v) {
    __nv_bfloat16 h = __float2bfloat16_rn(v);
    float hf = __bfloat162float(h);
    __nv_bfloat16 l = __float2bfloat16_rn(v - hf);
    return ((uint32_t)__bfloat16_as_ushort(h) << 16) | __bfloat16_as_ushort(l);
}

// split float2 into mma-operand pairs: hi = (bf16(v.x) | bf16(v.y)<<16)
__device__ __forceinline__ void pksplit2(float2 v, uint32_t& hi, uint32_t& lo) {
    __nv_bfloat16 h0 = __float2bfloat16_rn(v.x);
    __nv_bfloat16 h1 = __float2bfloat16_rn(v.y);
    __nv_bfloat16 l0 = __float2bfloat16_rn(v.x - __bfloat162float(h0));
    __nv_bfloat16 l1 = __float2bfloat16_rn(v.y - __bfloat162float(h1));
    hi = (uint32_t)__bfloat16_as_ushort(h0) |
         ((uint32_t)__bfloat16_as_ushort(h1) << 16);
    lo = (uint32_t)__bfloat16_as_ushort(l0) |
         ((uint32_t)__bfloat16_as_ushort(l1) << 16);
}

// acquire/release atomics (no MEMBAR)
__device__ __forceinline__ unsigned atom_add_acqrel(unsigned* p, unsigned v) {
    unsigned old;
    asm volatile("atom.acq_rel.gpu.global.add.u32 %0, [%1], %2;"
                 : "=r"(old) : "l"(p), "r"(v) : "memory");
    return old;
}
__device__ __forceinline__ unsigned ld_acq(const unsigned* p) {
    unsigned v;
    asm volatile("ld.acquire.gpu.global.u32 %0, [%1];"
                 : "=r"(v) : "l"(p) : "memory");
    return v;
}
__device__ __forceinline__ void red_release(unsigned* p, unsigned v) {
    asm volatile("red.release.gpu.global.add.u32 [%0], %1;"
                 :: "l"(p), "r"(v) : "memory");
}

// fast gating (MUFU-based, overflow-safe)
__device__ __forceinline__ float ftanh_(float x) {
    float ax = fabsf(x);
    float e = __expf(-2.f * ax);
    float r = __fdividef(1.f - e, 1.f + e);
    return copysignf(r, x);
}
__device__ __forceinline__ float fsigm(float x) {
    return fmaf(0.5f, ftanh_(0.5f * x), 0.5f);
}

// ---------------- fused pack: x split + gate weights + fc_w/w0/w1 ----------
__global__ void pack_all_kernel(const float* __restrict__ x,
                            const float* __restrict__ fw, const float* __restrict__ iw,
                            const float* __restrict__ uw, const float* __restrict__ ow,
                            const float* __restrict__ fb, const float* __restrict__ ib,
                            const float* __restrict__ ub, const float* __restrict__ ob,
                            const float* __restrict__ fcw, const float* __restrict__ w0,
                            const float* __restrict__ w1)
{
    int idx = blockIdx.x * 256 + threadIdx.x;      // grid covers TB_*D_/4
    {   // x split-pack (all blocks)
        float4 v = ((const float4*)x)[idx];
        uint4 o;
        o.x = pk(v.x); o.y = pk(v.y); o.z = pk(v.z); o.w = pk(v.w);
        ((uint4*)g_xp)[idx] = o;
    }
    if (idx < G4_ * H_) {
        int row = idx >> 8;
        int k   = idx & 255;
        int gate = row >> 8;
        int rl   = row & 255;
        const float* w = (gate == 0) ? fw : (gate == 1) ? iw : (gate == 2) ? uw : ow;
        g_Wxp[idx] = pk(w[rl * (2 * H_) + k]);
        g_Wh[idx]  = w[rl * (2 * H_) + H_ + k];
        if (idx < G4_) {
            int g2 = idx >> 8;
            const float* b = (g2 == 0) ? fb : (g2 == 1) ? ib : (g2 == 2) ? ub : ob;
            g_bias[idx] = b[idx & 255];
        }
        if (idx < H_ * D_ / 4) {
            float4 v = ((const float4*)fcw)[idx];
            uint4 o; o.x = pk(v.x); o.y = pk(v.y); o.z = pk(v.z); o.w = pk(v.w);
            ((uint4*)g_fcwp)[idx] = o;
        }
        if (idx < H_ * H_ / 4) {
            float4 v = ((const float4*)w0)[idx];
            uint4 o; o.x = pk(v.x); o.y = pk(v.y); o.z = pk(v.z); o.w = pk(v.w);
            ((uint4*)g_w0p)[idx] = o;
            v = ((const float4*)w1)[idx];
            o.x = pk(v.x); o.y = pk(v.y); o.z = pk(v.z); o.w = pk(v.w);
            ((uint4*)g_w1p)[idx] = o;
        }
    }
}

// ================= bf16x3 mma.sync GEMM (R13-proven config) =================
// CTA tile 128x128, 256 thr (8 warps, warp tile 32x64). K-chunk 32.
#define STAGE_BYTES 32768
#define B_OFF 16384

__global__ void __launch_bounds__(256, 1) gemm_mma(
    const uint32_t* __restrict__ A, const uint32_t* __restrict__ W,
    const float* __restrict__ bias, void* __restrict__ Cv,
    int K, int N, int act, int outpk)
{
    extern __shared__ char smc[];
    uint32_t sbase = smem_u32(smc);
    int tid = threadIdx.x, lane = tid & 31, wid = tid >> 5;
    int m0 = blockIdx.y * 128, n0 = blockIdx.x * 128;
    int wm = (wid >> 1) * 32, wn = (wid & 1) * 64;

    int q = lane >> 3, r = lane & 7;
    int rA0 = wm + (q & 1) * 8 + r;
    int cuA = q >> 1;
    int rBb = wn + (q >> 1) * 8 + r;
    int cuB = q & 1;

    int lrow = tid >> 1, lseg = (tid & 1) * 16;
    const uint32_t* Ag = A + (size_t)(m0 + lrow) * K + lseg;
    const uint32_t* Wg = W + (size_t)(n0 + lrow) * K + lseg;
    uint32_t sh[4], sl[4];
#pragma unroll
    for (int j = 0; j < 4; j++) {
        int col = lseg + 4 * j;
        int unit = col >> 3;
        int off = (col & 4) * 2;
        sh[j] = lrow * 128 + (((unit    ) ^ (lrow & 7)) << 4) + off;
        sl[j] = lrow * 128 + (((unit + 4) ^ (lrow & 7)) << 4) + off;
    }

    float c[2][8][4];
#pragma unroll
    for (int mt = 0; mt < 2; mt++)
#pragma unroll
        for (int f = 0; f < 8; f++)
#pragma unroll
            for (int e = 0; e < 4; e++) c[mt][f][e] = 0.f;

    int nc = K >> 5;

    {
        char* st = smc;
#pragma unroll
        for (int j = 0; j < 4; j++) {
            uint4 v = *(const uint4*)&Ag[4 * j];
            uint2 hi, lo;
            hi.x = __byte_perm(v.x, v.y, 0x7632);
            lo.x = __byte_perm(v.x, v.y, 0x5410);
            hi.y = __byte_perm(v.z, v.w, 0x7632);
            lo.y = __byte_perm(v.z, v.w, 0x5410);
            *(uint2*)(st + sh[j]) = hi;
            *(uint2*)(st + sl[j]) = lo;
            v = *(const uint4*)&Wg[4 * j];
            hi.x = __byte_perm(v.x, v.y, 0x7632);
            lo.x = __byte_perm(v.x, v.y, 0x5410);
            hi.y = __byte_perm(v.z, v.w, 0x7632);
            lo.y = __byte_perm(v.z, v.w, 0x5410);
            *(uint2*)(st + B_OFF + sh[j]) = hi;
            *(uint2*)(st + B_OFF + sl[j]) = lo;
        }
    }
    __syncthreads();

#pragma unroll 1
    for (int ch = 0; ch < nc; ch++) {
        uint4 va[4], vw[4];
        if (ch + 1 < nc) {
            const uint32_t* Ap = Ag + (ch + 1) * 32;
            const uint32_t* Wp = Wg + (ch + 1) * 32;
#pragma unroll
            for (int j = 0; j < 4; j++) {
                va[j] = *(const uint4*)&Ap[4 * j];
                vw[j] = *(const uint4*)&Wp[4 * j];
            }
        }

        uint32_t st = sbase + (ch & 1) * STAGE_BYTES;
#pragma unroll
        for (int kk = 0; kk < 2; kk++) {
            uint32_t ah[2][4], al[2][4], bh[8][2], bl[8][2];
#pragma unroll
            for (int mt = 0; mt < 2; mt++) {
                int row = rA0 + mt * 16;
                ldsm4(ah[mt], st + row * 128 + (((cuA + kk * 2    ) ^ (row & 7)) << 4));
                ldsm4(al[mt], st + row * 128 + (((cuA + kk * 2 + 4) ^ (row & 7)) << 4));
            }
#pragma unroll
            for (int nt = 0; nt < 4; nt++) {
                int row = rBb + nt * 16;
                uint32_t t4[4];
                ldsm4(t4, st + B_OFF + row * 128 + (((cuB + kk * 2    ) ^ (row & 7)) << 4));
                bh[nt * 2][0] = t4[0]; bh[nt * 2][1] = t4[1];
                bh[nt * 2 + 1][0] = t4[2]; bh[nt * 2 + 1][1] = t4[3];
                ldsm4(t4, st + B_OFF + row * 128 + (((cuB + kk * 2 + 4) ^ (row & 7)) << 4));
                bl[nt * 2][0] = t4[0]; bl[nt * 2][1] = t4[1];
                bl[nt * 2 + 1][0] = t4[2]; bl[nt * 2 + 1][1] = t4[3];
            }
#pragma unroll
            for (int mt = 0; mt < 2; mt++)
#pragma unroll
                for (int f = 0; f < 8; f++) {
                    mma_bf16(c[mt][f], ah[mt], bh[f]);
                    mma_bf16(c[mt][f], ah[mt], bl[f]);
                    mma_bf16(c[mt][f], al[mt], bh[f]);
                }
        }

        if (ch + 1 < nc) {
            char* stw = smc + ((ch + 1) & 1) * STAGE_BYTES;
#pragma unroll
            for (int j = 0; j < 4; j++) {
                uint2 hi, lo;
                hi.x = __byte_perm(va[j].x, va[j].y, 0x7632);
                lo.x = __byte_perm(va[j].x, va[j].y, 0x5410);
                hi.y = __byte_perm(va[j].z, va[j].w, 0x7632);
                lo.y = __byte_perm(va[j].z, va[j].w, 0x5410);
                *(uint2*)(stw + sh[j]) = hi;
                *(uint2*)(stw + sl[j]) = lo;
                hi.x = __byte_perm(vw[j].x, vw[j].y, 0x7632);
                lo.x = __byte_perm(vw[j].x, vw[j].y, 0x5410);
                hi.y = __byte_perm(vw[j].z, vw[j].w, 0x7632);
                lo.y = __byte_perm(vw[j].z, vw[j].w, 0x5410);
                *(uint2*)(stw + B_OFF + sh[j]) = hi;
                *(uint2*)(stw + B_OFF + sl[j]) = lo;
            }
            __syncthreads();
        }
    }

#pragma unroll
    for (int mt = 0; mt < 2; mt++) {
        int row = m0 + wm + mt * 16 + (lane >> 2);
#pragma unroll
        for (int f = 0; f < 8; f++) {
            int col = n0 + wn + f * 8 + (lane & 3) * 2;
            float b0 = __ldg(&bias[col]), b1 = __ldg(&bias[col + 1]);
            float v0 = c[mt][f][0] + b0, v1 = c[mt][f][1] + b1;
            float v2 = c[mt][f][2] + b0, v3 = c[mt][f][3] + b1;
            if (act == 1) {
                v0 = tanhf(v0); v1 = tanhf(v1); v2 = tanhf(v2); v3 = tanhf(v3);
            } else if (act == 2) {
                v0 = fmaxf(v0, 0.f); v1 = fmaxf(v1, 0.f);
                v2 = fmaxf(v2, 0.f); v3 = fmaxf(v3, 0.f);
            }
            if (outpk) {
                uint32_t* Cp = (uint32_t*)Cv;
                uint2 p01; p01.x = pk(v0); p01.y = pk(v1);
                uint2 p23; p23.x = pk(v2); p23.y = pk(v3);
                *(uint2*)&Cp[(size_t)row * N + col] = p01;
                *(uint2*)&Cp[(size_t)(row + 8) * N + col] = p23;
            } else {
                float* Cf = (float*)Cv;
                *(float2*)&Cf[(size_t)row * N + col] = make_float2(v0, v1);
                *(float2*)&Cf[(size_t)(row + 8) * N + col] = make_float2(v2, v3);
            }
        }
    }
}

// ---------------- recurrence: tensor-core inner GEMM, smem-resident Wh -----
// barrier over the 8 CTAs of one batch group; acq_rel atomics, no MEMBAR.
__device__ __forceinline__ void group_barrier(int grp, unsigned* s_gen_p) {
    __syncthreads();
    if (threadIdx.x == 0) {
        unsigned my = *s_gen_p;
        unsigned t = atom_add_acqrel(&g_bar_in[grp * 32], 1u);
        if (t == 7u) {
            g_bar_in[grp * 32] = 0;
            red_release(&g_bar_gen[grp * 32], 1u);
        } else {
            while (ld_acq(&g_bar_gen[grp * 32]) == my) { }
        }
        *s_gen_p = my + 1;
    }
    __syncthreads();
}

// smem layout (dynamic): whHi[64KB] | whLo[64KB] | hxs[8*260 u32] | red[128*9 f]
// Wh tiles: per (warp w, ktile kt): 16x16 bf16 tile as 4 8x8 matrices
// (m0 = rows 0-7 x k0-7, m1 = rows 8-15 x k0-7, m2 = rows 0-7 x k8-15,
//  m3 = rows 8-15 x k8-15), 32 rows x 16B -> ldsm4(tile + lane*16).
#define RSM_WHLO  65536
#define RSM_HXS   131072
#define RSM_RED   (131072 + 8320)
#define RSM_TOTAL (131072 + 8320 + 4608 + 64)
#define HXS_STRIDE 260

__global__ void __launch_bounds__(256, 1) recur_kernel()
{
    extern __shared__ char rsm[];
    uint32_t sbase = smem_u32(rsm);
    uint32_t* hxs = (uint32_t*)(rsm + RSM_HXS);
    float* red = (float*)(rsm + RSM_RED);
    __shared__ unsigned s_gen;

    int tid = threadIdx.x;
    int lane = tid & 31, w = tid >> 5;
    int cta = blockIdx.x;
    int bs = cta >> 3, cs = cta & 7;

    // ---- one-time: stage Wh slice into smem as ldsm-native hi/lo tiles ----
    for (int e2 = tid; e2 < 128 * 128; e2 += 256) {
        int s = e2 >> 7;                 // slice row 0..127
        int kp = (e2 & 127) * 2;         // k pair 0..254
        int R = (s >> 5) * 256 + cs * 32 + (s & 31);
        uint32_t hi, lo;
        pksplit2(*(const float2*)&g_Wh[(size_t)R * H_ + kp], hi, lo);
        int ww = s >> 4, sl = s & 15;
        int kt = kp >> 4, kk = kp & 15;
        int m = ((sl >> 3) & 1) | (((kk >> 3) & 1) << 1);
        int off = (ww * 16 + kt) * 512 + (m * 8 + (sl & 7)) * 16 + (kk & 7) * 2;
        *(uint32_t*)(rsm + off) = hi;
        *(uint32_t*)(rsm + RSM_WHLO + off) = lo;
    }

    // lane decode (matches m16n8k16 A-frag / red scatter of R13)
    int r0 = lane >> 2;
    int q2 = (lane & 3) * 2;
    int s0 = w * 16 + r0;
    int s1 = s0 + 8;
    uint32_t whA = sbase + w * 8192 + lane * 16;          // hi tiles base
    uint32_t whAlo = whA + RSM_WHLO;

    int b    = tid >> 5;
    int bidx = bs * 8 + b;
    int col  = cs * 32 + lane;
    float cx = 0.f;

    g_hxp[bidx * H_ + col] = 0u;
    if (tid == 0) s_gen = ld_acq(&g_bar_gen[bs * 32]);
    group_barrier(bs, &s_gen);

    for (int t = 0; t < T_; t++) {
        int cur = t & 1, nxt = cur ^ 1;

        const float* gxrow = &g_gx[((size_t)t * B_ + bidx) * G4_ + col];
        float gx0 = __ldg(&gxrow[0]);
        float gx1 = __ldg(&gxrow[256]);
        float gx2 = __ldg(&gxrow[512]);
        float gx3 = __ldg(&gxrow[768]);

        {
            const uint4* src = (const uint4*)&g_hxp[cur * (B_ * H_) + bs * 8 * H_];
            uint4 v0 = __ldcg(&src[tid * 2]);
            uint4 v1 = __ldcg(&src[tid * 2 + 1]);
            int f = tid * 8;
            int n = f >> 8, k = f & 255;
            *(uint4*)&hxs[n * HXS_STRIDE + k]     = v0;
            *(uint4*)&hxs[n * HXS_STRIDE + k + 4] = v1;
        }
        __syncthreads();

        // 4 independent accumulator chains; A-frags streamed from smem
        float c4[4][4];
#pragma unroll
        for (int i = 0; i < 4; i++)
#pragma unroll
            for (int e = 0; e < 4; e++) c4[i][e] = 0.f;
#pragma unroll
        for (int kt = 0; kt < 16; kt++) {
            uint32_t ahi[4], alo[4];
            ldsm4(ahi, whA   + kt * 512);
            ldsm4(alo, whAlo + kt * 512);
            int kb = kt * 16 + q2;
            uint2 u0 = *(const uint2*)&hxs[r0 * HXS_STRIDE + kb];
            uint2 u1 = *(const uint2*)&hxs[r0 * HXS_STRIDE + kb + 8];
            uint32_t bh[2], bl[2];
            bh[0] = __byte_perm(u0.x, u0.y, 0x7632);
            bl[0] = __byte_perm(u0.x, u0.y, 0x5410);
            bh[1] = __byte_perm(u1.x, u1.y, 0x7632);
            bl[1] = __byte_perm(u1.x, u1.y, 0x5410);
            float* cc = c4[kt & 3];
            mma_bf16(cc, ahi, bh);
            mma_bf16(cc, ahi, bl);
            mma_bf16(cc, alo, bh);
        }
        float c[4];
#pragma unroll
        for (int e = 0; e < 4; e++)
            c[e] = (c4[0][e] + c4[1][e]) + (c4[2][e] + c4[3][e]);

        red[s0 * 9 + q2]     = c[0];
        red[s0 * 9 + q2 + 1] = c[1];
        red[s1 * 9 + q2]     = c[2];
        red[s1 * 9 + q2 + 1] = c[3];
        __syncthreads();

        float sf = red[(0 * 32 + lane) * 9 + b];
        float si = red[(1 * 32 + lane) * 9 + b];
        float su = red[(2 * 32 + lane) * 9 + b];
        float so = red[(3 * 32 + lane) * 9 + b];

        float fg = fsigm(sf + gx0);
        float ig = fsigm(si + gx1);
        float ug = ftanh_(su + gx2);
        float og = fsigm(so + gx3);
        cx = fg * cx + ig * ug;
        float h = og * ftanh_(cx);

        uint32_t hp = pk(h);
        g_hxp[nxt * (B_ * H_) + bidx * H_ + col] = hp;
        g_hsb[((size_t)t * B_ + bidx) * H_ + col] = hp;

        group_barrier(bs, &s_gen);
    }
}

// ---------------- final tiny projection to 2 logits ------------------------
__global__ void __launch_bounds__(256) final_kernel(
    const float* __restrict__ z, const float* __restrict__ w2,
    const float* __restrict__ b2, float* __restrict__ out)
{
    __shared__ float w[512];
    __shared__ float bb[2];
    int tid = threadIdx.x;
    w[tid] = w2[tid];
    w[tid + 256] = w2[tid + 256];
    if (tid < 2) bb[tid] = b2[tid];
    __syncthreads();

    int row = blockIdx.x * 256 + tid;
    const float4* zp = (const float4*)&z[(size_t)row * H_];
    float a0 = 0.f, a1 = 0.f;
#pragma unroll
    for (int qq = 0; qq < 64; qq++) {
        float4 v = zp[qq];
        a0 = fmaf(v.x, w[4 * qq + 0], a0);
        a0 = fmaf(v.y, w[4 * qq + 1], a0);
        a0 = fmaf(v.z, w[4 * qq + 2], a0);
        a0 = fmaf(v.w, w[4 * qq + 3], a0);
        a1 = fmaf(v.x, w[256 + 4 * qq + 0], a1);
        a1 = fmaf(v.y, w[256 + 4 * qq + 1], a1);
        a1 = fmaf(v.z, w[256 + 4 * qq + 2], a1);
        a1 = fmaf(v.w, w[256 + 4 * qq + 3], a1);
    }
    out[row * 2 + 0] = a0 + bb[0];
    out[row * 2 + 1] = a1 + bb[1];
}

// ---------------- host -----------------------------------------------------
extern "C" void kernel_launch(void* const* d_in, const int* in_sizes, int n_in,
                              void* d_out, int out_size)
{
    const float* x    = (const float*)d_in[0];
    const float* fc_w = (const float*)d_in[1];
    const float* fc_b = (const float*)d_in[2];
    const float* fw   = (const float*)d_in[3];
    const float* fb   = (const float*)d_in[4];
    const float* iw   = (const float*)d_in[5];
    const float* ib   = (const float*)d_in[6];
    const float* uw   = (const float*)d_in[7];
    const float* ub   = (const float*)d_in[8];
    const float* ow   = (const float*)d_in[9];
    const float* ob   = (const float*)d_in[10];
    const float* w0   = (const float*)d_in[11];
    const float* b0   = (const float*)d_in[12];
    const float* w1   = (const float*)d_in[13];
    const float* b1   = (const float*)d_in[14];
    const float* w2   = (const float*)d_in[15];
    const float* b2   = (const float*)d_in[16];
    float* out = (float*)d_out;

    void *p_xp, *p_hb, *p_gx, *p_hsb, *p_z0b, *p_z1;
    void *p_wxp, *p_bias, *p_fcwp, *p_w0p, *p_w1p;
    cudaGetSymbolAddress(&p_xp,   g_xp);
    cudaGetSymbolAddress(&p_hb,   g_hb);
    cudaGetSymbolAddress(&p_gx,   g_gx);
    cudaGetSymbolAddress(&p_hsb,  g_hsb);
    cudaGetSymbolAddress(&p_z0b,  g_z0b);
    cudaGetSymbolAddress(&p_z1,   g_z1);
    cudaGetSymbolAddress(&p_wxp,  g_Wxp);
    cudaGetSymbolAddress(&p_bias, g_bias);
    cudaGetSymbolAddress(&p_fcwp, g_fcwp);
    cudaGetSymbolAddress(&p_w0p,  g_w0p);
    cudaGetSymbolAddress(&p_w1p,  g_w1p);

    cudaFuncSetAttribute(gemm_mma, cudaFuncAttributeMaxDynamicSharedMemorySize,
                         2 * STAGE_BYTES);
    cudaFuncSetAttribute(recur_kernel, cudaFuncAttributeMaxDynamicSharedMemorySize,
                         RSM_TOTAL);

    // slot 0: fused pack (x split + all weight packing)
    pack_all_kernel<<<(TB_ * D_ / 4) / 256, 256>>>(
        x, fw, iw, uw, ow, fb, ib, ub, ob, fc_w, w0, w1);
    // slot 1: h = tanh(x @ fc_w^T + fc_b)
    gemm_mma<<<dim3(H_ / 128, TB_ / 128), 256, 2 * STAGE_BYTES>>>(
        (const uint32_t*)p_xp, (const uint32_t*)p_fcwp, fc_b, p_hb, D_, H_, 1, 1);
    // slot 2: gx = h @ Wx^T + bias
    gemm_mma<<<dim3(G4_ / 128, TB_ / 128), 256, 2 * STAGE_BYTES>>>(
        (const uint32_t*)p_hb, (const uint32_t*)p_wxp, (const float*)p_bias,
        p_gx, H_, G4_, 0, 0);
    // slot 3 (profiled): LSTM recurrence
    recur_kernel<<<128, 256, RSM_TOTAL>>>();
    // slots 4-5: classifier
    gemm_mma<<<dim3(H_ / 128, TB_ / 128), 256, 2 * STAGE_BYTES>>>(
        (const uint32_t*)p_hsb, (const uint32_t*)p_w0p, b0, p_z0b, H_, H_, 2, 1);
    gemm_mma<<<dim3(H_ / 128, TB_ / 128), 256, 2 * STAGE_BYTES>>>(
        (const uint32_t*)p_z0b, (const uint32_t*)p_w1p, b1, p_z1, H_, H_, 2, 0);
    // slot 6
    final_kernel<<<TB_ / 256, 256>>>((const float*)p_z1, w2, b2, out);
}